// round 17
// baseline (speedup 1.0000x reference)
#include <cuda_runtime.h>

#define NN 50000
#define EE 800000
#define DD 128
#define SLOPE 0.2f
#define ZBLK 196   // blocks covering NN in k_zero_detect

// ---------------- device scratch (static, no allocation) ----------------
__device__ float g_xl[NN * DD];
__device__ float g_xr[NN * DD];
__device__ float g_h1[NN * DD];
__device__ int   g_rowptr[NN + 1];
__device__ int   g_cnt[NN];
__device__ int   g_cursor[NN];
__device__ int   g_srcs[EE];
__device__ int   g_is64;
__device__ unsigned g_wfrag[4 * 16384];   // fragment-major, pre-tf32 W (4 mats)

__device__ __forceinline__ unsigned tf32cvt(float f) {
    unsigned r;
    asm("cvt.rna.tf32.f32 %0, %1;" : "=r"(r) : "f"(f));
    return r;
}

// ---------------- zero + dtype probe + W fragment prep (merged) ----------------
// Blocks [0, ZBLK): zero g_cnt (+ block 0: int64 probe).
// Blocks [ZBLK, ZBLK+256): rewrite the 4 weight matrices into fragment-major,
// pre-converted tf32 order: g_wfrag[mat*16384 + ((kk*2+nw)*32+lane)*16 + j]
//  = tf32(W[kk*8 + t + h*4][nw*64 + nt*8 + g]), lane=(g<<2)|t, j=(nt<<1)|h.
__global__ void k_zero_detect(const int* __restrict__ ei32,
                              const float* __restrict__ W0, const float* __restrict__ W1,
                              const float* __restrict__ W2, const float* __restrict__ W3) {
    int b = blockIdx.x;
    if (b < ZBLK) {
        int i = b * 256 + threadIdx.x;
        if (i < NN) g_cnt[i] = 0;
        if (b == 0 && threadIdx.x < 32) {
            int nz = 0;
#pragma unroll
            for (int q = 0; q < 2; q++)
                nz |= (ei32[2 * (threadIdx.x * 2 + q) + 1] != 0);
            unsigned any = __ballot_sync(0xffffffffu, nz);
            if (threadIdx.x == 0) g_is64 = (any == 0u) ? 1 : 0;
        }
    } else {
        int idx = (b - ZBLK) * 256 + threadIdx.x;       // 0..65535
        int mat = idx >> 14;
        int rem = idx & 16383;
        int kk = rem >> 10;
        int nw = (rem >> 9) & 1;
        int lane = (rem >> 4) & 31;
        int j = rem & 15;
        int g = lane >> 2, t = lane & 3, nt = j >> 1, h = j & 1;
        int row = kk * 8 + t + h * 4;
        int col = nw * 64 + nt * 8 + g;
        const float* Wm = (mat == 0) ? W0 : (mat == 1) ? W1 : (mat == 2) ? W2 : W3;
        g_wfrag[idx] = tf32cvt(Wm[row * 128 + col]);
    }
}

__device__ __forceinline__ int ld_edge(const int* ei32, int elem, int is64) {
    int v;
    if (is64) {
        long long t = ((const long long*)ei32)[elem];
        v = (int)t;
    } else {
        v = ei32[elem];
    }
    v = v < 0 ? 0 : (v >= NN ? NN - 1 : v);
    return v;
}

// ---------------- CSR build ----------------
__global__ void k_hist(const int* __restrict__ ei32) {
    int e = blockIdx.x * blockDim.x + threadIdx.x;
    int is64 = g_is64;
    if (e < EE) {
        int d = ld_edge(ei32, EE + e, is64);
        atomicAdd(&g_cnt[d], 1);
    }
}

__global__ __launch_bounds__(1024) void k_scan() {
    const int CHUNK = 49;
    __shared__ int wsums[32];
    __shared__ int s_total;
    int tid = threadIdx.x, lane = tid & 31, wid = tid >> 5;
    int base = tid * CHUNK;

    int sum = 0;
#pragma unroll
    for (int i = 0; i < CHUNK; i++) {
        int idx = base + i;
        if (idx < NN) sum += g_cnt[idx];
    }

    int x = sum;
#pragma unroll
    for (int off = 1; off < 32; off <<= 1) {
        int t = __shfl_up_sync(0xffffffffu, x, off);
        if (lane >= off) x += t;
    }
    if (lane == 31) wsums[wid] = x;
    __syncthreads();
    if (wid == 0) {
        int y = wsums[lane];
        int z = y;
#pragma unroll
        for (int off = 1; off < 32; off <<= 1) {
            int t = __shfl_up_sync(0xffffffffu, z, off);
            if (lane >= off) z += t;
        }
        wsums[lane] = z - y;
        if (lane == 31) s_total = z;
    }
    __syncthreads();

    int run = wsums[wid] + (x - sum);
#pragma unroll
    for (int i = 0; i < CHUNK; i++) {
        int idx = base + i;
        if (idx < NN) {
            int c = g_cnt[idx];
            g_rowptr[idx] = run;
            g_cursor[idx] = run;
            run += c;
        }
    }
    if (tid == 0) g_rowptr[NN] = s_total;
}

__global__ void k_scatter(const int* __restrict__ ei32) {
    int e = blockIdx.x * blockDim.x + threadIdx.x;
    int is64 = g_is64;
    if (e < EE) {
        int d = ld_edge(ei32, EE + e, is64);
        int s = ld_edge(ei32, e, is64);
        int pos = atomicAdd(&g_cursor[d], 1);
        g_srcs[pos] = s;
    }
}

// ---------------- tf32 tensor-core GEMM ----------------
// 64x128 tile; A via cp.async smem double-buffer (swizzled); B fragments read
// DIRECTLY from L2 in fragment-major pre-converted layout: 4x LDG.128 per k8,
// zero LDS and zero cvt on the B path.
__device__ __forceinline__ void cpasync16(unsigned dst_smem, const void* src, int sz) {
    asm volatile("cp.async.ca.shared.global [%0], [%1], 16, %2;"
                 :: "r"(dst_smem), "l"(src), "r"(sz));
}

__global__ __launch_bounds__(256) void k_gemm(
    const float* __restrict__ x, int x_from_h1, int mat0,
    const float* __restrict__ b0, const float* __restrict__ b1)
{
    __shared__ float xs[2][64 * 32];    // swizzled A tiles (64 rows x 32 k)

    const float* xx = x_from_h1 ? g_h1 : x;
    const float* bb = blockIdx.y ? b1 : b0;
    float* out      = blockIdx.y ? g_xr : g_xl;
    const int mat   = mat0 + (int)blockIdx.y;

    const int row0 = blockIdx.x * 64;
    const int tid = threadIdx.x;
    const int wid = tid >> 5;
    const int lane = tid & 31;
    const int g = lane >> 2;
    const int t = lane & 3;

    const int mwarp = wid & 3;    // 0..3 -> 16 rows each
    const int nwarp = wid >> 2;   // 0..1 -> 64 cols each

    // fragment-major W base for this (mat, nwarp, lane)
    const unsigned* wf = g_wfrag + (mat << 14) + nwarp * 512 + lane * 16;

    float acc[8][4];
#pragma unroll
    for (int nt = 0; nt < 8; nt++)
#pragma unroll
        for (int c = 0; c < 4; c++) acc[nt][c] = 0.f;

    auto load_chunk = [&](int kc, int buf) {
#pragma unroll
        for (int it = 0; it < 2; it++) {
            int idx = tid + it * 256;      // 0..511
            int m = idx >> 3;              // 0..63
            int kq = idx & 7;
            int gr = row0 + m;
            unsigned dst = (unsigned)__cvta_generic_to_shared(
                &xs[buf][m * 32 + (((kq + m) & 7) << 2)]);
            const float* src = &xx[(size_t)(gr < NN ? gr : 0) * 128 + kc + kq * 4];
            cpasync16(dst, src, gr < NN ? 16 : 0);
        }
        asm volatile("cp.async.commit_group;");
    };

    load_chunk(0, 0);

#pragma unroll
    for (int c = 0; c < 4; c++) {
        int buf = c & 1;
        if (c < 3) {
            load_chunk((c + 1) * 32, buf ^ 1);
            asm volatile("cp.async.wait_group 1;");
        } else {
            asm volatile("cp.async.wait_group 0;");
        }
        __syncthreads();

        const float* xsb = xs[buf];
#pragma unroll
        for (int k8 = 0; k8 < 4; k8++) {
            int kb = k8 * 8;
            int kk = c * 4 + k8;
            // B fragments: 4 coalesced LDG.128 from L2 (pre-converted tf32)
            const uint4* p = (const uint4*)(wf + kk * 1024);
            uint4 q0 = p[0], q1 = p[1], q2 = p[2], q3 = p[3];

            unsigned af[4];
            {
                int m0 = mwarp * 16 + g;
                int m1 = m0 + 8;
                int klo = kb + t, khi = kb + t + 4;
                af[0] = tf32cvt(xsb[m0 * 32 + ((((klo >> 2) + m0) & 7) << 2) + (klo & 3)]);
                af[1] = tf32cvt(xsb[m1 * 32 + ((((klo >> 2) + m1) & 7) << 2) + (klo & 3)]);
                af[2] = tf32cvt(xsb[m0 * 32 + ((((khi >> 2) + m0) & 7) << 2) + (khi & 3)]);
                af[3] = tf32cvt(xsb[m1 * 32 + ((((khi >> 2) + m1) & 7) << 2) + (khi & 3)]);
            }

#define MMA_NT(ntv, blo, bhi)                                                    \
            asm volatile(                                                        \
                "mma.sync.aligned.m16n8k8.row.col.f32.tf32.tf32.f32 "            \
                "{%0,%1,%2,%3}, {%4,%5,%6,%7}, {%8,%9}, {%0,%1,%2,%3};"          \
                : "+f"(acc[ntv][0]), "+f"(acc[ntv][1]),                          \
                  "+f"(acc[ntv][2]), "+f"(acc[ntv][3])                           \
                : "r"(af[0]), "r"(af[1]), "r"(af[2]), "r"(af[3]),                \
                  "r"(blo), "r"(bhi))

            MMA_NT(0, q0.x, q0.y);
            MMA_NT(1, q0.z, q0.w);
            MMA_NT(2, q1.x, q1.y);
            MMA_NT(3, q1.z, q1.w);
            MMA_NT(4, q2.x, q2.y);
            MMA_NT(5, q2.z, q2.w);
            MMA_NT(6, q3.x, q3.y);
            MMA_NT(7, q3.z, q3.w);
#undef MMA_NT
        }
        __syncthreads();
    }

#pragma unroll
    for (int nt = 0; nt < 8; nt++) {
        int col = nwarp * 64 + nt * 8 + 2 * t;
        float bx = bb[col], by = bb[col + 1];
        int r0 = row0 + mwarp * 16 + g;
        int r1 = r0 + 8;
        if (r0 < NN) {
            float2 v = make_float2(acc[nt][0] + bx, acc[nt][1] + by);
            *(float2*)&out[r0 * 128 + col] = v;
        }
        if (r1 < NN) {
            float2 v = make_float2(acc[nt][2] + bx, acc[nt][3] + by);
            *(float2*)&out[r1 * 128 + col] = v;
        }
    }
}

// ---------------- fused attention + aggregation (R12-measured-best form) ----------------
// Two 16-lane edge streams per warp; lane owns 8 dims; in-loop shfl ladder
// under the half-warp mask (halves may diverge in trip count).
__global__ __launch_bounds__(256) void k_aggregate(
    const float* __restrict__ att, const float* __restrict__ bias,
    float* __restrict__ out, int out_to_h1)
{
    int gw = (blockIdx.x * blockDim.x + threadIdx.x) >> 5;
    int lane = threadIdx.x & 31;
    if (gw >= NN) return;

    int half = lane >> 4;
    int hl = lane & 15;
    unsigned hmask = 0xFFFFu << (half * 16);

    float* o = out_to_h1 ? g_h1 : out;

    int beg = g_rowptr[gw];
    int end = g_rowptr[gw + 1];

    const float* xrp = &g_xr[(size_t)gw * 128 + hl * 8];
    float4 xr0 = *(const float4*)&xrp[0];
    float4 xr1 = *(const float4*)&xrp[4];
    float4 at0 = *(const float4*)&att[hl * 8 + 0];
    float4 at1 = *(const float4*)&att[hl * 8 + 4];

    float4 ac0 = make_float4(0.f, 0.f, 0.f, 0.f);
    float4 ac1 = make_float4(0.f, 0.f, 0.f, 0.f);
    float wsum = 0.f;

    int j0 = beg + half;
    int sA = (j0 < end) ? g_srcs[j0] : 0;
    for (int j = j0; j < end; j += 2) {
        int s = sA;
        if (j + 2 < end) sA = g_srcs[j + 2];
        const float* xp = &g_xl[(size_t)s * 128 + hl * 8];
        float4 xv0 = *(const float4*)&xp[0];
        float4 xv1 = *(const float4*)&xp[4];

        float z, part = 0.f;
        z = xv0.x + xr0.x; z = z > 0.f ? z : SLOPE * z; part += z * at0.x;
        z = xv0.y + xr0.y; z = z > 0.f ? z : SLOPE * z; part += z * at0.y;
        z = xv0.z + xr0.z; z = z > 0.f ? z : SLOPE * z; part += z * at0.z;
        z = xv0.w + xr0.w; z = z > 0.f ? z : SLOPE * z; part += z * at0.w;
        z = xv1.x + xr1.x; z = z > 0.f ? z : SLOPE * z; part += z * at1.x;
        z = xv1.y + xr1.y; z = z > 0.f ? z : SLOPE * z; part += z * at1.y;
        z = xv1.z + xr1.z; z = z > 0.f ? z : SLOPE * z; part += z * at1.z;
        z = xv1.w + xr1.w; z = z > 0.f ? z : SLOPE * z; part += z * at1.w;

        part += __shfl_xor_sync(hmask, part, 8);
        part += __shfl_xor_sync(hmask, part, 4);
        part += __shfl_xor_sync(hmask, part, 2);
        part += __shfl_xor_sync(hmask, part, 1);

        float w = __expf(part);
        ac0.x += w * xv0.x; ac0.y += w * xv0.y; ac0.z += w * xv0.z; ac0.w += w * xv0.w;
        ac1.x += w * xv1.x; ac1.y += w * xv1.y; ac1.z += w * xv1.z; ac1.w += w * xv1.w;
        wsum += w;
    }

    __syncwarp(0xffffffffu);

    ac0.x += __shfl_xor_sync(0xffffffffu, ac0.x, 16);
    ac0.y += __shfl_xor_sync(0xffffffffu, ac0.y, 16);
    ac0.z += __shfl_xor_sync(0xffffffffu, ac0.z, 16);
    ac0.w += __shfl_xor_sync(0xffffffffu, ac0.w, 16);
    ac1.x += __shfl_xor_sync(0xffffffffu, ac1.x, 16);
    ac1.y += __shfl_xor_sync(0xffffffffu, ac1.y, 16);
    ac1.z += __shfl_xor_sync(0xffffffffu, ac1.z, 16);
    ac1.w += __shfl_xor_sync(0xffffffffu, ac1.w, 16);
    wsum  += __shfl_xor_sync(0xffffffffu, wsum, 16);

    if (half == 0) {
        float inv = 1.f / fmaxf(wsum, 1e-16f);
        float4 b0 = *(const float4*)&bias[hl * 8 + 0];
        float4 b1 = *(const float4*)&bias[hl * 8 + 4];
        float* op = &o[(size_t)gw * 128 + hl * 8];
        float4 r0, r1;
        r0.x = fmaxf(ac0.x * inv + b0.x, 0.f);
        r0.y = fmaxf(ac0.y * inv + b0.y, 0.f);
        r0.z = fmaxf(ac0.z * inv + b0.z, 0.f);
        r0.w = fmaxf(ac0.w * inv + b0.w, 0.f);
        r1.x = fmaxf(ac1.x * inv + b1.x, 0.f);
        r1.y = fmaxf(ac1.y * inv + b1.y, 0.f);
        r1.z = fmaxf(ac1.z * inv + b1.z, 0.f);
        r1.w = fmaxf(ac1.w * inv + b1.w, 0.f);
        *(float4*)&op[0] = r0;
        *(float4*)&op[4] = r1;
    }
}

// ---------------- launch ----------------
extern "C" void kernel_launch(void* const* d_in, const int* in_sizes, int n_in,
                              void* d_out, int out_size) {
    const float* x0    = (const float*)d_in[0];
    const int*   ei32  = (const int*)d_in[1];
    const float* Wl1   = (const float*)d_in[2];
    const float* bl1   = (const float*)d_in[3];
    const float* Wr1   = (const float*)d_in[4];
    const float* br1   = (const float*)d_in[5];
    const float* att1  = (const float*)d_in[6];
    const float* bias1 = (const float*)d_in[7];
    const float* Wl2   = (const float*)d_in[8];
    const float* bl2   = (const float*)d_in[9];
    const float* Wr2   = (const float*)d_in[10];
    const float* br2   = (const float*)d_in[11];
    const float* att2  = (const float*)d_in[12];
    const float* bias2 = (const float*)d_in[13];
    float* out = (float*)d_out;

    dim3 ggrid((NN + 63) / 64, 2);

    // CSR build + W-fragment prep + layer-1 gemm; gemm1 at profiled slot (index 3).
    k_zero_detect<<<ZBLK + 256, 256>>>(ei32, Wl1, Wr1, Wl2, Wr2);
    k_hist<<<(EE + 255) / 256, 256>>>(ei32);
    k_scan<<<1, 1024>>>();
    k_gemm<<<ggrid, 256>>>(x0, 0, 0, bl1, br1);
    k_scatter<<<(EE + 255) / 256, 256>>>(ei32);

    k_aggregate<<<(NN * 32 + 255) / 256, 256>>>(att1, bias1, out, 1);

    k_gemm<<<ggrid, 256>>>(x0, 1, 2, bl2, br2);
    k_aggregate<<<(NN * 32 + 255) / 256, 256>>>(att2, bias2, out, 0);
}